// round 3
// baseline (speedup 1.0000x reference)
#include <cuda_runtime.h>
#include <cstdint>

// SpectralGraphConv: B=2, N=8192, Cin=8, Cout=8, modes=64
// Key insight: only U[:, 0:64] matters (2MB of the 256MB matrix), w_imag is dead.
//
// Pipeline (one CUDA graph, 3 nodes, fully deterministic — no atomics):
//   k1  : partial xf[chunk][b][m][i] over n-chunks           -> g_partial
//   k1b : reduce chunks + spectral mixing with w_real        -> g_F
//   k2  : out[b,n,j] = sum_m U[n,m] * F[b,m,j]               -> d_out

#define NN      8192
#define CINC    8
#define COUTC   8
#define MODESC  64
#define K1B     128   // k1 blocks (n-chunks)
#define CHUNK   64    // n rows per k1 block

// Scratch: __device__ globals (no allocation). Fully rewritten every launch.
__device__ __align__(16) float g_partial[K1B * 1024];   // [chunk][(b*64+m)*8+i]
__device__ __align__(16) float g_F[1024];               // [(b*64+m)*8+j]

#define FMA4(acc, s, v) do { \
    (acc).x += (s) * (v).x; (acc).y += (s) * (v).y; \
    (acc).z += (s) * (v).z; (acc).w += (s) * (v).w; } while (0)

// ---------------------------------------------------------------------------
// k1: per-chunk partial sums  xf_part[c][b][m][i] = sum_{n in chunk} U[n,m] x[b,n,i]
// 128 blocks x 256 threads. Thread t -> (m = t&63, b = (t>>6)&1, half = t>>7).
// ---------------------------------------------------------------------------
__global__ __launch_bounds__(256, 1)
void k1_partial(const float* __restrict__ x, const float* __restrict__ eig) {
    __shared__ __align__(16) float Us[CHUNK * MODESC];      // 16 KB  [row][m]
    __shared__ __align__(16) float xs[2 * CHUNK * CINC];    //  4 KB  [b][row][i]
    __shared__ __align__(16) float red[128 * 8];            //  4 KB

    const int tid = threadIdx.x;
    const int n0  = blockIdx.x * CHUNK;

    // Stage U tile: 64 rows x 64 floats (256B contiguous per row)
    float4* Us4 = reinterpret_cast<float4*>(Us);
    #pragma unroll
    for (int k = 0; k < 4; k++) {
        int f   = tid + k * 256;        // float4 index, 0..1023
        int row = f >> 4;
        int c4  = f & 15;
        Us4[f] = *reinterpret_cast<const float4*>(
            eig + (size_t)(n0 + row) * NN + c4 * 4);
    }
    // Stage x tile: 2 batches x 64 rows x 8 floats = 256 float4
    float4* xs4 = reinterpret_cast<float4*>(xs);
    {
        int f   = tid;
        int b   = f >> 7;
        int rem = f & 127;
        int row = rem >> 1;
        int h   = rem & 1;
        xs4[f] = *reinterpret_cast<const float4*>(
            x + ((size_t)(b * NN + n0 + row)) * CINC + h * 4);
    }
    __syncthreads();

    const int m    = tid & 63;
    const int b    = (tid >> 6) & 1;
    const int half = tid >> 7;

    float4 a0 = make_float4(0.f, 0.f, 0.f, 0.f);
    float4 a1 = make_float4(0.f, 0.f, 0.f, 0.f);

    const float4* xrow = reinterpret_cast<const float4*>(xs) + (b * CHUNK + half * 32) * 2;
    const float*  ucol = Us + (half * 32) * MODESC + m;

    #pragma unroll
    for (int r = 0; r < 32; r++) {
        float  u   = ucol[r * MODESC];       // conflict-free: lanes span m
        float4 xv0 = xrow[r * 2 + 0];        // broadcast within warp
        float4 xv1 = xrow[r * 2 + 1];
        FMA4(a0, u, xv0);
        FMA4(a1, u, xv1);
    }

    // combine the two n-halves, write partials
    float4* red4 = reinterpret_cast<float4*>(red);
    __syncthreads();  // compute done; red region free to (re)use
    if (half == 1) {
        red4[(tid - 128) * 2 + 0] = a0;
        red4[(tid - 128) * 2 + 1] = a1;
    }
    __syncthreads();
    if (half == 0) {
        float4 b0 = red4[tid * 2 + 0];
        float4 b1 = red4[tid * 2 + 1];
        a0.x += b0.x; a0.y += b0.y; a0.z += b0.z; a0.w += b0.w;
        a1.x += b1.x; a1.y += b1.y; a1.z += b1.z; a1.w += b1.w;
        // (b*64+m) == tid for half==0 threads
        float4* gp = reinterpret_cast<float4*>(g_partial) + blockIdx.x * 256 + tid * 2;
        gp[0] = a0;
        gp[1] = a1;
    }
}

// ---------------------------------------------------------------------------
// k1b: reduce 128 chunks -> xf, then mix with w_real -> g_F
// 4 blocks x 256 threads. Thread owns one v = (b*64+m)*8+i:
//   xf[v] = sum_c g_partial[c][v]   (128 coalesced loads, serial, deterministic)
// Then per-(b,m) octet of threads computes F[b,m,j] from xf octet in smem.
// ---------------------------------------------------------------------------
__global__ __launch_bounds__(256, 1)
void k1b_reduce_mix(const float* __restrict__ w_real) {
    __shared__ float xf[256];

    const int t = threadIdx.x;
    const int v = blockIdx.x * 256 + t;     // 0..1023

    float sum = 0.f;
    #pragma unroll 8
    for (int c = 0; c < K1B; c++)
        sum += g_partial[(size_t)c * 1024 + v];
    xf[t] = sum;
    __syncthreads();

    const int j    = v & 7;
    const int m    = (v >> 3) & 63;
    const int base = t & ~7;                // start of this (b,m) octet in xf[]

    float f = 0.f;
    #pragma unroll
    for (int i = 0; i < 8; i++)
        f += xf[base + i] * w_real[(i * 8 + j) * MODESC + m];
    g_F[v] = f;
}

// ---------------------------------------------------------------------------
// k2: out[b,n,j] = sum_{m<64} U[n,m] * F[b,m,j]
// 128 blocks x 128 threads; one thread per (b,n) row.
// U row preloaded into 16 float4 regs (MLP=16 hides DRAM latency);
// F broadcast from smem (conflict-free: index independent of n).
// ---------------------------------------------------------------------------
__global__ __launch_bounds__(128, 1)
void k2_out(const float* __restrict__ eig, float* __restrict__ out) {
    __shared__ __align__(16) float Fs[1024];

    const int tid = threadIdx.x;
    float4* Fs4 = reinterpret_cast<float4*>(Fs);
    const float4* gF4 = reinterpret_cast<const float4*>(g_F);
    Fs4[tid * 2 + 0] = gF4[tid * 2 + 0];
    Fs4[tid * 2 + 1] = gF4[tid * 2 + 1];
    __syncthreads();

    const int r = blockIdx.x * 128 + tid;   // 0..16383
    const int b = r >> 13;
    const int n = r & (NN - 1);

    const float4* U4 = reinterpret_cast<const float4*>(eig + (size_t)n * NN);
    float4 u[16];
    #pragma unroll
    for (int mc = 0; mc < 16; mc++) u[mc] = U4[mc];   // 16 independent LDG.128

    float4 a0 = make_float4(0.f, 0.f, 0.f, 0.f);
    float4 a1 = make_float4(0.f, 0.f, 0.f, 0.f);
    const float4* Fb = Fs4 + b * 128;       // [m][2] float4

    #pragma unroll
    for (int mc = 0; mc < 16; mc++) {
        const float uv[4] = { u[mc].x, u[mc].y, u[mc].z, u[mc].w };
        #pragma unroll
        for (int k = 0; k < 4; k++) {
            int m = mc * 4 + k;
            float4 f0 = Fb[m * 2 + 0];
            float4 f1 = Fb[m * 2 + 1];
            FMA4(a0, uv[k], f0);
            FMA4(a1, uv[k], f1);
        }
    }

    float4* o = reinterpret_cast<float4*>(out + (size_t)r * COUTC);
    o[0] = a0;
    o[1] = a1;
}

// ---------------------------------------------------------------------------
extern "C" void kernel_launch(void* const* d_in, const int* in_sizes, int n_in,
                              void* d_out, int out_size) {
    const float* x      = (const float*)d_in[0];  // (2, 8192, 8)
    const float* eig    = (const float*)d_in[1];  // (8192, 8192)
    const float* w_real = (const float*)d_in[2];  // (8, 8, 64)
    // d_in[3] (w_imag) is mathematically dead: input is real, only real part kept.
    float* out = (float*)d_out;                   // (2, 8192, 8)

    k1_partial<<<K1B, 256>>>(x, eig);
    k1b_reduce_mix<<<4, 256>>>(w_real);
    k2_out<<<128, 128>>>(eig, out);
}